// round 11
// baseline (speedup 1.0000x reference)
#include <cuda_runtime.h>
#include <math_constants.h>

#define BATCH 8
#define H 1080
#define W 1920
#define NPIX (H * W)
#define NTOT (BATCH * NPIX)

#define BX 128
#define BY 24
#define NTHR 256

// ---- K1 tiles (float4 words) ----
#define XROWS (BY + 6)   // 30 ; x col c stored at float idx c+4, c in [-4,139]
#define XW4   36         // 144 floats
#define SROWS (BY + 2)   // 26 ; smoothed col cs at float idx cs+1
#define SW4   34         // 136 floats

// ---- K2 tiles ----
#define MROWS (BY + 6)   // 30 ; mag col c at float idx c+8
#define MW4   36
#define DROWS (BY + 4)   // 28 ; dir bytes: col c at byte idx c+8
#define BW4   36
// 2-bit state tiles: px p -> word (p+16)/16, lane (p+16)%16, bits [2l,2l+1]
// s_0: 28 rows, word w stored at col w+1 (cols 0,11 are zero pads), stride 12
// s_1: 26 rows (row s = tile row s-1), words 0..9, stride 12
#define S0ROWS 28
#define S1ROWS 26
#define SSTRIDE 12

// Scratch (device globals — no allocations allowed)
__device__ float g_mag[NTOT];
__device__ unsigned char g_dir[NTOT];

// ---------------------------------------------------------------------------
// K1: fused x/255 -> gaussian 5x5 (zero pad) -> sobel (zero pad) -> mag/ang/cls
// Per-pixel FP accumulation order identical to previous passing kernels.
// ---------------------------------------------------------------------------
__global__ __launch_bounds__(NTHR) void k1(const float* __restrict__ x,
                                           float* __restrict__ out_mag,
                                           float* __restrict__ out_ang) {
    __shared__ float4 s_x[XROWS][XW4];
    __shared__ float4 s_s[SROWS][SW4];

    const int x0 = blockIdx.x * BX, y0 = blockIdx.y * BY, b = blockIdx.z;
    const int tid = threadIdx.x;
    const float* img = x + (size_t)b * NPIX;

    // ---- Phase A: load x tile (halo, zero outside image), vectorized ----
    for (int g = tid; g < XROWS * XW4; g += NTHR) {
        int r = g / XW4, j = g - r * XW4;
        int gy = y0 + r - 3;
        int gx = x0 + 4 * j - 4;
        float4 v = make_float4(0.f, 0.f, 0.f, 0.f);
        if ((unsigned)gy < (unsigned)H) {
            const float* row = img + (size_t)gy * W;
            if (gx >= 0 && gx + 3 < W) {
                v = *(const float4*)(row + gx);
            } else {
                float* vp = &v.x;
#pragma unroll
                for (int k = 0; k < 4; k++)
                    if ((unsigned)(gx + k) < (unsigned)W) vp[k] = row[gx + k];
            }
        }
        s_x[r][j] = v;
    }
    __syncthreads();

    // ---- Phase B: gaussian into s_s (8 px per iteration) ----
    for (int g = tid; g < SROWS * 17; g += NTHR) {
        int r = g / 17, h = g - r * 17;
        int cs = 8 * h - 1;           // smoothed col group base, cs in [-1,127]
        int gy = y0 + r - 1;
        const float G[25] = {
            2.0f/159.0f, 4.0f/159.0f,  5.0f/159.0f, 4.0f/159.0f, 2.0f/159.0f,
            4.0f/159.0f, 9.0f/159.0f, 12.0f/159.0f, 9.0f/159.0f, 4.0f/159.0f,
            5.0f/159.0f,12.0f/159.0f, 15.0f/159.0f,12.0f/159.0f, 5.0f/159.0f,
            4.0f/159.0f, 9.0f/159.0f, 12.0f/159.0f, 9.0f/159.0f, 4.0f/159.0f,
            2.0f/159.0f, 4.0f/159.0f,  5.0f/159.0f, 4.0f/159.0f, 2.0f/159.0f };
        float res[8] = {0.f,0.f,0.f,0.f,0.f,0.f,0.f,0.f};
#pragma unroll
        for (int dy = 0; dy < 5; dy++) {
            __align__(16) float f[16];
            *(float4*)(f +  0) = s_x[r + dy][2*h];
            *(float4*)(f +  4) = s_x[r + dy][2*h + 1];
            *(float4*)(f +  8) = s_x[r + dy][2*h + 2];
            *(float4*)(f + 12) = s_x[r + dy][2*h + 3];
            // x col (cs+j-2+dx) at float idx 8h+1+j+dx -> local f[1+j+dx]
#pragma unroll
            for (int j = 0; j < 8; j++)
#pragma unroll
                for (int dx = 0; dx < 5; dx++)
                    res[j] = fmaf(f[1 + j + dx], G[dy * 5 + dx], res[j]);
        }
        float4 sv0, sv1;
        float* sp0 = &sv0.x;
        float* sp1 = &sv1.x;
#pragma unroll
        for (int j = 0; j < 8; j++) {
            int gx = x0 + cs + j;
            float v = ((unsigned)gy < (unsigned)H && (unsigned)gx < (unsigned)W)
                      ? res[j] * (1.0f / 255.0f) : 0.0f;
            if (j < 4) sp0[j] = v; else sp1[j - 4] = v;
        }
        s_s[r][2*h]     = sv0;
        s_s[r][2*h + 1] = sv1;
    }
    __syncthreads();

    // ---- Phase C: sobel + mag + angle, 4 px per iteration ----
    for (int g = tid; g < BY * 32; g += NTHR) {
        int r = g >> 5, gc = g & 31;
        int c = 4 * gc;
        __align__(16) float fm[8], f0[8], fp[8];
        *(float4*)(fm)     = s_s[r][gc];     *(float4*)(fm + 4) = s_s[r][gc + 1];
        *(float4*)(f0)     = s_s[r + 1][gc]; *(float4*)(f0 + 4) = s_s[r + 1][gc + 1];
        *(float4*)(fp)     = s_s[r + 2][gc]; *(float4*)(fp + 4) = s_s[r + 2][gc + 1];

        float4 vmag, vmag255, vang;
        unsigned int dirw = 0;
#pragma unroll
        for (int j = 0; j < 4; j++) {
            float a00 = fm[j], a01 = fm[j + 1], a02 = fm[j + 2];
            float a10 = f0[j],                  a12 = f0[j + 2];
            float a20 = fp[j], a21 = fp[j + 1], a22 = fp[j + 2];

            float gxv = 0.0f;
            gxv = fmaf(a00, -0.125f, gxv);
            gxv = fmaf(a02,  0.125f, gxv);
            gxv = fmaf(a10, -0.25f,  gxv);
            gxv = fmaf(a12,  0.25f,  gxv);
            gxv = fmaf(a20, -0.125f, gxv);
            gxv = fmaf(a22,  0.125f, gxv);

            float gyv = 0.0f;
            gyv = fmaf(a00, -0.125f, gyv);
            gyv = fmaf(a01, -0.25f,  gyv);
            gyv = fmaf(a02, -0.125f, gyv);
            gyv = fmaf(a20,  0.125f, gyv);
            gyv = fmaf(a21,  0.25f,  gyv);
            gyv = fmaf(a22,  0.125f, gyv);

            float mag = sqrtf(gxv * gxv + gyv * gyv + 1e-6f);
            float ang = atan2f(gyv, gxv);

            float v = ang + CUDART_PI_F;
            const float TWOPI = 2.0f * CUDART_PI_F;
            if (v >= TWOPI) v -= TWOPI;
            float deg = v * (180.0f / CUDART_PI_F);
            int rr = (int)rintf(deg / 45.0f);
            int cls = (rr & 7) & 3;

            float adeg = deg;
            if (adeg >= 180.0f) adeg -= 180.0f;
            if (adeg >= 180.0f) adeg -= 180.0f;

            (&vmag.x)[j]    = mag;
            (&vmag255.x)[j] = mag * 255.0f;
            (&vang.x)[j]    = adeg;
            dirw |= (unsigned int)cls << (8 * j);
        }
        size_t base = (size_t)b * NPIX + (size_t)(y0 + r) * W + (x0 + c);
        *(float4*)(g_mag + base)        = vmag;
        *(float4*)(out_mag + base)      = vmag255;
        *(float4*)(out_ang + base)      = vang;
        *(unsigned int*)(g_dir + base)  = dirw;
    }
}

// ---------------------------------------------------------------------------
// K2: NMS (wrap neighbors, incl. ref's class-1 n_up bug) + 2 hysteresis
//     iterations on 2-bit packed states (16 px / word).
// ---------------------------------------------------------------------------
__global__ __launch_bounds__(NTHR) void k2(float* __restrict__ out_edges) {
    __shared__ float4       s_m[MROWS][MW4];
    __shared__ unsigned int s_d[DROWS][BW4];
    __shared__ unsigned int s_0[S0ROWS][SSTRIDE];
    __shared__ unsigned int s_1[S1ROWS][SSTRIDE];

    const int x0 = blockIdx.x * BX, y0 = blockIdx.y * BY, b = blockIdx.z;
    const int tid = threadIdx.x;
    const float* m = g_mag + (size_t)b * NPIX;
    const unsigned char* dd = g_dir + (size_t)b * NPIX;

    // ---- A1: mag tile with wrap (jnp.roll semantics) ----
    for (int g = tid; g < MROWS * MW4; g += NTHR) {
        int r = g / MW4, j = g - r * MW4;
        int gy = y0 + r - 3;
        if (gy < 0) gy += H; else if (gy >= H) gy -= H;
        int gx = x0 + 4 * j - 8;
        const float* row = m + (size_t)gy * W;
        float4 v;
        if (gx >= 0 && gx + 3 < W) {
            v = *(const float4*)(row + gx);
        } else {
            float* vp = &v.x;
#pragma unroll
            for (int k = 0; k < 4; k++) {
                int t = gx + k;
                if (t < 0) t += W; else if (t >= W) t -= W;
                vp[k] = row[t];
            }
        }
        s_m[r][j] = v;
    }
    // ---- A2: dir tile (zero outside image) ----
    for (int g = tid; g < DROWS * BW4; g += NTHR) {
        int r = g / BW4, j = g - r * BW4;
        int gy = y0 + r - 2;
        int gx = x0 + 4 * j - 8;
        unsigned int v = 0;
        if ((unsigned)gy < (unsigned)H) {
            const unsigned char* row = dd + (size_t)gy * W;
            if (gx >= 0 && gx + 3 < W) {
                v = *(const unsigned int*)(row + gx);
            } else {
#pragma unroll
                for (int k = 0; k < 4; k++)
                    if ((unsigned)(gx + k) < (unsigned)W)
                        v |= (unsigned int)row[gx + k] << (8 * k);
            }
        }
        s_d[r][j] = v;
    }
    // ---- A3: zero-fill s_0 (pads + body; body bytes overwritten in B) ----
    for (int g = tid; g < S0ROWS * SSTRIDE; g += NTHR)
        ((unsigned int*)s_0)[g] = 0u;
    __syncthreads();

    // ---- B: NMS + double threshold -> packed 2-bit states (byte per 4 px) --
    // Encoding: 0=none, 1(01)=low, 2(10)=edge.
    const float HIGHT = 150.0f / 255.0f;
    const float LOWT  = 50.0f  / 255.0f;
    unsigned char* s0b = (unsigned char*)s_0;
    for (int g = tid; g < DROWS * 34; g += NTHR) {
        int r = g / 34, gi = g - r * 34;
        int cc = 4 * gi - 4;                 // state col group base in [-4,128]
        int gy = y0 + (r - 2);
        __align__(16) float um[12], cm[12], dm[12];
        *(float4*)(um) = s_m[r][gi];     *(float4*)(um+4) = s_m[r][gi+1];     *(float4*)(um+8) = s_m[r][gi+2];
        *(float4*)(cm) = s_m[r+1][gi];   *(float4*)(cm+4) = s_m[r+1][gi+1];   *(float4*)(cm+8) = s_m[r+1][gi+2];
        *(float4*)(dm) = s_m[r+2][gi];   *(float4*)(dm+4) = s_m[r+2][gi+1];   *(float4*)(dm+8) = s_m[r+2][gi+2];
        unsigned int dw = s_d[r][gi + 1];
        bool rowok = (unsigned)gy < (unsigned)H;
        unsigned int byte = 0;
#pragma unroll
        for (int j = 0; j < 4; j++) {
            // mag col (cc+j+d) at local idx j+4+d
            float c0 = cm[j + 4];
            int cls = (int)((dw >> (8 * j)) & 0xFF);
            float n1 = (cls == 0) ? cm[j + 5]             // R
                     : (cls == 1) ? dm[j + 5]             // DR (n_d1)
                     : (cls == 2) ? dm[j + 4]             // D
                                  : dm[j + 3];            // DL (n_d3)
            float n2 = (cls == 0) ? cm[j + 3]             // L
                     : (cls == 3) ? um[j + 5]             // UR (n_d4)
                                  : um[j + 4];            // U (cls 1 ref-bug & 2)
            int st = 0;
            if ((c0 > n1) && (c0 > n2))
                st = (c0 > HIGHT) ? 2 : ((c0 >= LOWT) ? 1 : 0);
            int gx = x0 + cc + j;
            if (!(rowok && (unsigned)gx < (unsigned)W)) st = 0;
            byte |= (unsigned int)st << (2 * j);
        }
        // px group cc: byte index (cc+16)/4 = gi+3 ; row stride 48 bytes
        s0b[r * (SSTRIDE * 4) + gi + 3] = (unsigned char)byte;
    }
    __syncthreads();

    // ---- C: hysteresis iter 1 on packed words (16 px / iteration) ----
    // s_1 row r = tile row r-1, word w (px 16(w-1)-16+... same packing as s_0)
    for (int g = tid; g < S1ROWS * 10; g += NTHR) {
        int r = g / 10, w = g - r * 10;
        unsigned int nb = 0, ctr = 0;
#pragma unroll
        for (int q = 0; q < 3; q++) {
            unsigned int p = s_0[r + q][w];
            unsigned int c = s_0[r + q][w + 1];
            unsigned int n = s_0[r + q][w + 2];
            unsigned int rowv = c | __funnelshift_l(p, c, 2) | __funnelshift_r(c, n, 2);
            nb |= rowv;
            if (q == 1) ctr = c;
        }
        unsigned int promo = (ctr & 0x55555555u) & ((nb & 0xAAAAAAAAu) >> 1);
        s_1[r][w] = ctr + promo;     // 01 + 01 = 10 : low -> edge
    }
    __syncthreads();

    // ---- D: hysteresis iter 2 + edges output (16 px / iteration) ----
    for (int g = tid; g < BY * 8; g += NTHR) {
        int t = g >> 3;              // tile row
        int w = (g & 7) + 1;         // word 1..8  (px 16(w-1) .. 16w-1)
        unsigned int nb = 0, ctr = 0;
#pragma unroll
        for (int q = 0; q < 3; q++) {
            unsigned int p = s_1[t + q][w - 1];
            unsigned int c = s_1[t + q][w];
            unsigned int n = s_1[t + q][w + 1];
            unsigned int rowv = c | __funnelshift_l(p, c, 2) | __funnelshift_r(c, n, 2);
            nb |= rowv;
            if (q == 1) ctr = c;
        }
        unsigned int promo = (ctr & 0x55555555u) & ((nb & 0xAAAAAAAAu) >> 1);
        unsigned int res = ctr + promo;

        size_t base = (size_t)b * NPIX + (size_t)(y0 + t) * W + (x0 + 16 * (w - 1));
#pragma unroll
        for (int k = 0; k < 4; k++) {
            float4 o;
            float* op = &o.x;
#pragma unroll
            for (int j = 0; j < 4; j++)
                op[j] = ((res >> (2 * (4 * k + j) + 1)) & 1u) ? 255.0f : 0.0f;
            *(float4*)(out_edges + base + 4 * k) = o;
        }
    }
}

// ---------------------------------------------------------------------------
// Launch
// ---------------------------------------------------------------------------
extern "C" void kernel_launch(void* const* d_in, const int* in_sizes, int n_in,
                              void* d_out, int out_size) {
    const float* x = (const float*)d_in[0];
    float* out = (float*)d_out;
    float* out_edges = out;
    float* out_mag   = out + (size_t)NTOT;
    float* out_ang   = out + (size_t)2 * NTOT;

    dim3 blk(NTHR, 1, 1);
    dim3 grd(W / BX, H / BY, BATCH);   // 15 x 45 x 8

    k1<<<grd, blk>>>(x, out_mag, out_ang);
    k2<<<grd, blk>>>(out_edges);
}

// round 12
// speedup vs baseline: 1.8176x; 1.8176x over previous
#include <cuda_runtime.h>
#include <math_constants.h>

#define BATCH 8
#define H 1080
#define W 1920
#define NPIX (H * W)
#define NTOT (BATCH * NPIX)

#define BX 128
#define BY 24
#define NTHR 256

// ---- K1 tiles (float4 words) ----
#define XROWS (BY + 6)   // 30 ; x col c stored at float idx c+4, c in [-4,139]
#define XW4   36         // 144 floats
#define SROWS (BY + 2)   // 26 ; smoothed col cs at float idx cs+1
#define SW4   34         // 136 floats

// ---- K2 tiles ----
#define MROWS (BY + 6)   // 30 ; mag col c at float idx c+8, c in [-8,135]
#define MW4   36         // 144 floats
#define DROWS (BY + 4)   // 28 ; byte tiles: col c at byte idx c+8
#define BW4   36         // 144 bytes = 36 words
#define S1ROWS (BY + 2)  // 26

// Scratch (device globals — no allocations allowed)
__device__ float g_mag[NTOT];
__device__ unsigned char g_dir[NTOT];

// ---------------------------------------------------------------------------
// K1: fused x/255 -> gaussian 5x5 (zero pad) -> sobel (zero pad) -> mag/ang/cls
// (identical to the round-10 passing kernel)
// ---------------------------------------------------------------------------
__global__ __launch_bounds__(NTHR) void k1(const float* __restrict__ x,
                                           float* __restrict__ out_mag,
                                           float* __restrict__ out_ang) {
    __shared__ float4 s_x[XROWS][XW4];
    __shared__ float4 s_s[SROWS][SW4];

    const int x0 = blockIdx.x * BX, y0 = blockIdx.y * BY, b = blockIdx.z;
    const int tid = threadIdx.x;
    const float* img = x + (size_t)b * NPIX;

    // ---- Phase A: load x tile (halo, zero outside image), vectorized ----
    for (int g = tid; g < XROWS * XW4; g += NTHR) {
        int r = g / XW4, j = g - r * XW4;
        int gy = y0 + r - 3;
        int gx = x0 + 4 * j - 4;
        float4 v = make_float4(0.f, 0.f, 0.f, 0.f);
        if ((unsigned)gy < (unsigned)H) {
            const float* row = img + (size_t)gy * W;
            if (gx >= 0 && gx + 3 < W) {
                v = *(const float4*)(row + gx);
            } else {
                float* vp = &v.x;
#pragma unroll
                for (int k = 0; k < 4; k++)
                    if ((unsigned)(gx + k) < (unsigned)W) vp[k] = row[gx + k];
            }
        }
        s_x[r][j] = v;
    }
    __syncthreads();

    // ---- Phase B: gaussian into s_s (4 px per iteration) ----
    for (int g = tid; g < SROWS * 33; g += NTHR) {
        int r = g / 33, gc = g - r * 33;
        int cs = 4 * gc - 1;          // smoothed col group base, cs in [-1,127]
        int gy = y0 + r - 1;
        const float G[25] = {
            2.0f/159.0f, 4.0f/159.0f,  5.0f/159.0f, 4.0f/159.0f, 2.0f/159.0f,
            4.0f/159.0f, 9.0f/159.0f, 12.0f/159.0f, 9.0f/159.0f, 4.0f/159.0f,
            5.0f/159.0f,12.0f/159.0f, 15.0f/159.0f,12.0f/159.0f, 5.0f/159.0f,
            4.0f/159.0f, 9.0f/159.0f, 12.0f/159.0f, 9.0f/159.0f, 4.0f/159.0f,
            2.0f/159.0f, 4.0f/159.0f,  5.0f/159.0f, 4.0f/159.0f, 2.0f/159.0f };
        float res[4] = {0.f, 0.f, 0.f, 0.f};
#pragma unroll
        for (int dy = 0; dy < 5; dy++) {
            __align__(16) float f[12];
            *(float4*)(f + 0) = s_x[r + dy][gc];
            *(float4*)(f + 4) = s_x[r + dy][gc + 1];
            *(float4*)(f + 8) = s_x[r + dy][gc + 2];
            // x col (cs+j-2+dx) is at local idx 1+j+dx  (word base = float idx cs+1)
#pragma unroll
            for (int j = 0; j < 4; j++)
#pragma unroll
                for (int dx = 0; dx < 5; dx++)
                    res[j] = fmaf(f[1 + j + dx], G[dy * 5 + dx], res[j]);
        }
        float4 sv;
        float* sp = &sv.x;
#pragma unroll
        for (int j = 0; j < 4; j++) {
            int gx = x0 + cs + j;
            sp[j] = ((unsigned)gy < (unsigned)H && (unsigned)gx < (unsigned)W)
                    ? res[j] * (1.0f / 255.0f) : 0.0f;
        }
        s_s[r][gc] = sv;
    }
    __syncthreads();

    // ---- Phase C: sobel + mag + angle, 4 px per iteration ----
    for (int g = tid; g < BY * 32; g += NTHR) {
        int r = g >> 5, gc = g & 31;
        int c = 4 * gc;
        __align__(16) float fm[8], f0[8], fp[8];
        *(float4*)(fm)     = s_s[r][gc];     *(float4*)(fm + 4) = s_s[r][gc + 1];
        *(float4*)(f0)     = s_s[r + 1][gc]; *(float4*)(f0 + 4) = s_s[r + 1][gc + 1];
        *(float4*)(fp)     = s_s[r + 2][gc]; *(float4*)(fp + 4) = s_s[r + 2][gc + 1];

        float4 vmag, vmag255, vang;
        unsigned int dirw = 0;
#pragma unroll
        for (int j = 0; j < 4; j++) {
            float a00 = fm[j], a01 = fm[j + 1], a02 = fm[j + 2];
            float a10 = f0[j],                  a12 = f0[j + 2];
            float a20 = fp[j], a21 = fp[j + 1], a22 = fp[j + 2];

            float gxv = 0.0f;
            gxv = fmaf(a00, -0.125f, gxv);
            gxv = fmaf(a02,  0.125f, gxv);
            gxv = fmaf(a10, -0.25f,  gxv);
            gxv = fmaf(a12,  0.25f,  gxv);
            gxv = fmaf(a20, -0.125f, gxv);
            gxv = fmaf(a22,  0.125f, gxv);

            float gyv = 0.0f;
            gyv = fmaf(a00, -0.125f, gyv);
            gyv = fmaf(a01, -0.25f,  gyv);
            gyv = fmaf(a02, -0.125f, gyv);
            gyv = fmaf(a20,  0.125f, gyv);
            gyv = fmaf(a21,  0.25f,  gyv);
            gyv = fmaf(a22,  0.125f, gyv);

            float mag = sqrtf(gxv * gxv + gyv * gyv + 1e-6f);
            float ang = atan2f(gyv, gxv);

            float v = ang + CUDART_PI_F;
            const float TWOPI = 2.0f * CUDART_PI_F;
            if (v >= TWOPI) v -= TWOPI;
            float deg = v * (180.0f / CUDART_PI_F);
            int rr = (int)rintf(deg / 45.0f);
            int cls = (rr & 7) & 3;

            float adeg = deg;
            if (adeg >= 180.0f) adeg -= 180.0f;
            if (adeg >= 180.0f) adeg -= 180.0f;

            (&vmag.x)[j]    = mag;
            (&vmag255.x)[j] = mag * 255.0f;
            (&vang.x)[j]    = adeg;
            dirw |= (unsigned int)cls << (8 * j);
        }
        size_t base = (size_t)b * NPIX + (size_t)(y0 + r) * W + (x0 + c);
        *(float4*)(g_mag + base)        = vmag;
        *(float4*)(out_mag + base)      = vmag255;
        *(float4*)(out_ang + base)      = vang;
        *(unsigned int*)(g_dir + base)  = dirw;
    }
}

// ---------------------------------------------------------------------------
// K2: NMS (wrap neighbors, incl. ref's class-1 n_up bug) + 2 hysteresis
//     iterations, SIMD-in-word byte states, with data-dependent early-outs.
// ---------------------------------------------------------------------------
__global__ __launch_bounds__(NTHR) void k2(float* __restrict__ out_edges) {
    __shared__ float4       s_m[MROWS][MW4];
    __shared__ unsigned int s_d[DROWS][BW4];
    __shared__ unsigned int s_0[DROWS][BW4];
    __shared__ unsigned int s_1[S1ROWS][BW4];

    const int x0 = blockIdx.x * BX, y0 = blockIdx.y * BY, b = blockIdx.z;
    const int tid = threadIdx.x;
    const float* m = g_mag + (size_t)b * NPIX;
    const unsigned char* dd = g_dir + (size_t)b * NPIX;

    // ---- A1: mag tile with wrap (jnp.roll semantics) ----
    for (int g = tid; g < MROWS * MW4; g += NTHR) {
        int r = g / MW4, j = g - r * MW4;
        int gy = y0 + r - 3;
        if (gy < 0) gy += H; else if (gy >= H) gy -= H;
        int gx = x0 + 4 * j - 8;
        const float* row = m + (size_t)gy * W;
        float4 v;
        if (gx >= 0 && gx + 3 < W) {
            v = *(const float4*)(row + gx);
        } else {
            float* vp = &v.x;
#pragma unroll
            for (int k = 0; k < 4; k++) {
                int t = gx + k;
                if (t < 0) t += W; else if (t >= W) t -= W;
                vp[k] = row[t];
            }
        }
        s_m[r][j] = v;
    }
    // ---- A2: dir tile (zero outside image) ----
    for (int g = tid; g < DROWS * BW4; g += NTHR) {
        int r = g / BW4, j = g - r * BW4;
        int gy = y0 + r - 2;
        int gx = x0 + 4 * j - 8;
        unsigned int v = 0;
        if ((unsigned)gy < (unsigned)H) {
            const unsigned char* row = dd + (size_t)gy * W;
            if (gx >= 0 && gx + 3 < W) {
                v = *(const unsigned int*)(row + gx);
            } else {
#pragma unroll
                for (int k = 0; k < 4; k++)
                    if ((unsigned)(gx + k) < (unsigned)W)
                        v |= (unsigned int)row[gx + k] << (8 * k);
            }
        }
        s_d[r][j] = v;
    }
    // ---- A3: zero the unwritten edge words of s_0 ----
    for (int g = tid; g < DROWS * 2; g += NTHR)
        s_0[g >> 1][(g & 1) ? 35 : 0] = 0u;
    __syncthreads();

    // ---- B: NMS + double threshold -> packed states (2=edge,1=low,0=none) --
    // Early-out: st>0 requires center mag >= LOWT; test the 4 centers first.
    const float HIGHT = 150.0f / 255.0f;
    const float LOWT  = 50.0f  / 255.0f;
    for (int g = tid; g < DROWS * 34; g += NTHR) {
        int r = g / 34, gi = g - r * 34;

        float4 cv = s_m[r + 1][gi + 1];     // the 4 center mags (cm[4..7])
        float cmax = fmaxf(fmaxf(cv.x, cv.y), fmaxf(cv.z, cv.w));
        if (cmax < LOWT) {                   // whole group suppressed
            s_0[r][gi + 1] = 0u;
            continue;
        }

        int cc = 4 * gi - 4;                 // state col group base in [-4,128]
        int gy = y0 + (r - 2);
        __align__(16) float um[12], cm[12], dm[12];
        *(float4*)(um) = s_m[r][gi];     *(float4*)(um+4) = s_m[r][gi+1];     *(float4*)(um+8) = s_m[r][gi+2];
        *(float4*)(cm) = s_m[r+1][gi];                                        *(float4*)(cm+8) = s_m[r+1][gi+2];
        *(float4*)(cm+4) = cv;
        *(float4*)(dm) = s_m[r+2][gi];   *(float4*)(dm+4) = s_m[r+2][gi+1];   *(float4*)(dm+8) = s_m[r+2][gi+2];
        unsigned int dw = s_d[r][gi + 1];
        bool rowok = (unsigned)gy < (unsigned)H;
        unsigned int word = 0;
#pragma unroll
        for (int j = 0; j < 4; j++) {
            // mag col (cc+j+d) at local idx j+4+d
            float c0 = cm[j + 4];
            int cls = (int)((dw >> (8 * j)) & 0xFF);
            float n1 = (cls == 0) ? cm[j + 5]             // R
                     : (cls == 1) ? dm[j + 5]             // DR (n_d1)
                     : (cls == 2) ? dm[j + 4]             // D
                                  : dm[j + 3];            // DL (n_d3)
            float n2 = (cls == 0) ? cm[j + 3]             // L
                     : (cls == 3) ? um[j + 5]             // UR (n_d4)
                                  : um[j + 4];            // U (cls 1 ref-bug & 2)
            int st = 0;
            if ((c0 > n1) && (c0 > n2))
                st = (c0 > HIGHT) ? 2 : ((c0 >= LOWT) ? 1 : 0);
            int gx = x0 + cc + j;
            if (!(rowok && (unsigned)gx < (unsigned)W)) st = 0;
            word |= (unsigned int)st << (8 * j);
        }
        s_0[r][gi + 1] = word;
    }
    __syncthreads();

    // ---- C: hysteresis iter 1 (snapshot, zero pad), SIMD bytes ----
    // Early-out: only bytes == 1 can change; if none, pass through.
    for (int g = tid; g < S1ROWS * 34; g += NTHR) {
        int r = g / 34, gi = g - r * 34;
        unsigned int ctr = s_0[r + 1][gi + 1];
        unsigned int is1 = __vcmpeq4(ctr, 0x01010101u);
        if (is1 == 0u) { s_1[r][gi + 1] = ctr; continue; }
        unsigned int mx = 0;
#pragma unroll
        for (int q = 0; q < 3; q++) {
            unsigned int p = s_0[r + q][gi], c = s_0[r + q][gi + 1], n = s_0[r + q][gi + 2];
            unsigned int lft = __byte_perm(p, c, 0x6543);
            unsigned int rgt = __byte_perm(c, n, 0x4321);
            mx = __vmaxu4(mx, __vmaxu4(lft, __vmaxu4(c, rgt)));
        }
        unsigned int nb2 = __vcmpeq4(mx, 0x02020202u);
        s_1[r][gi + 1] = ctr + (is1 & nb2 & 0x01010101u);
    }
    __syncthreads();

    // ---- D: hysteresis iter 2 + edges output (float4 stores) ----
    for (int g = tid; g < BY * 32; g += NTHR) {
        int r = g >> 5, gi = g & 31;
        int cc = 4 * gi;
        unsigned int ctr = s_1[r + 1][gi + 2];
        unsigned int is1 = __vcmpeq4(ctr, 0x01010101u);
        unsigned int res = ctr;
        if (is1 != 0u) {
            unsigned int mx = 0;
#pragma unroll
            for (int q = 0; q < 3; q++) {
                unsigned int p = s_1[r + q][gi + 1], c = s_1[r + q][gi + 2], n = s_1[r + q][gi + 3];
                unsigned int lft = __byte_perm(p, c, 0x6543);
                unsigned int rgt = __byte_perm(c, n, 0x4321);
                mx = __vmaxu4(mx, __vmaxu4(lft, __vmaxu4(c, rgt)));
            }
            unsigned int nb2 = __vcmpeq4(mx, 0x02020202u);
            res = ctr + (is1 & nb2 & 0x01010101u);
        }

        float4 o;
        float* op = &o.x;
#pragma unroll
        for (int j = 0; j < 4; j++)
            op[j] = (((res >> (8 * j)) & 0xFF) == 2u) ? 255.0f : 0.0f;
        size_t base = (size_t)b * NPIX + (size_t)(y0 + r) * W + (x0 + cc);
        *(float4*)(out_edges + base) = o;
    }
}

// ---------------------------------------------------------------------------
// Launch
// ---------------------------------------------------------------------------
extern "C" void kernel_launch(void* const* d_in, const int* in_sizes, int n_in,
                              void* d_out, int out_size) {
    const float* x = (const float*)d_in[0];
    float* out = (float*)d_out;
    float* out_edges = out;
    float* out_mag   = out + (size_t)NTOT;
    float* out_ang   = out + (size_t)2 * NTOT;

    dim3 blk(NTHR, 1, 1);
    dim3 grd(W / BX, H / BY, BATCH);   // 15 x 45 x 8

    k1<<<grd, blk>>>(x, out_mag, out_ang);
    k2<<<grd, blk>>>(out_edges);
}

// round 14
// speedup vs baseline: 1.8532x; 1.0196x over previous
#include <cuda_runtime.h>
#include <math_constants.h>

#define BATCH 8
#define H 1080
#define W 1920
#define NPIX (H * W)
#define NTOT (BATCH * NPIX)

#define BX 128
#define BY 24
#define NTHR 256

// ---- K1 tiles (float4 words) ----
#define XROWS (BY + 6)   // 30 ; x col c stored at float idx c+4, c in [-4,139]
#define XW4   36         // 144 floats
#define SROWS (BY + 2)   // 26 ; smoothed col cs at float idx cs+1
#define SW4   34         // 136 floats

// ---- K2 tiles ----
#define MROWS (BY + 6)   // 30 ; mag col c at float idx c+8, c in [-8,135]
#define MW4   36         // 144 floats
#define DROWS (BY + 4)   // 28 ; byte tiles: col c at byte idx c+8
#define BW4   36         // 144 bytes = 36 words
#define S1ROWS (BY + 2)  // 26

// Scratch (device globals — no allocations allowed)
__device__ float g_mag[NTOT];
__device__ unsigned char g_dir[NTOT];

// ---------------------------------------------------------------------------
// Fast atan2 (Cephes-style): ~2e-7 rad accuracy, ~20 SASS inst.
// ---------------------------------------------------------------------------
__device__ __forceinline__ float fast_atan2f(float gy, float gx) {
    float ax = fabsf(gx), ay = fabsf(gy);
    float mx = fmaxf(ax, ay), mn = fminf(ax, ay);
    float t = (mx == 0.0f) ? 0.0f : __fdividef(mn, mx);   // [0,1]
    bool red = t > 0.41421356f;                            // tan(pi/8)
    float tr = __fdividef(t - 1.0f, t + 1.0f);             // (-0.2929, 0]
    float z = red ? tr : t;
    float s = z * z;
    float p = fmaf(s, fmaf(s, fmaf(s, 8.05374449538e-2f,
                                     -1.38776856032e-1f),
                               1.99777106479e-1f),
                     -3.33329491539e-1f);
    float a = fmaf(z * s, p, z);                           // atan(z)
    if (red) a += 0.78539816339744831f;                    // + pi/4
    if (ay > ax) a = 1.57079632679489662f - a;             // pi/2 - a
    if (gx < 0.0f) a = CUDART_PI_F - a;                    // pi - a
    return copysignf(a, gy);
}

// ---------------------------------------------------------------------------
// K1: fused x/255 -> gaussian 5x5 (zero pad) -> sobel (zero pad) -> mag/ang/cls
// ---------------------------------------------------------------------------
__global__ __launch_bounds__(NTHR) void k1(const float* __restrict__ x,
                                           float* __restrict__ out_mag,
                                           float* __restrict__ out_ang) {
    __shared__ float4 s_x[XROWS][XW4];
    __shared__ float4 s_s[SROWS][SW4];

    const int x0 = blockIdx.x * BX, y0 = blockIdx.y * BY, b = blockIdx.z;
    const int tid = threadIdx.x;
    const float* img = x + (size_t)b * NPIX;

    // Interior block: all tile accesses (x halo rows -3..+2 of loads spanning
    // gx in [x0-4, x0+139], gy in [y0-3, y0+26]) are fully inside the image.
    const bool interior = (x0 >= 4) && (x0 + 140 <= W) &&
                          (y0 >= 3) && (y0 + 27 <= H);

    // ---- Phase A: load x tile (halo), vectorized ----
    if (interior) {
        for (int g = tid; g < XROWS * XW4; g += NTHR) {
            int r = g / XW4, j = g - r * XW4;
            const float* row = img + (size_t)(y0 + r - 3) * W + (x0 - 4);
            s_x[r][j] = *(const float4*)(row + 4 * j);
        }
    } else {
        for (int g = tid; g < XROWS * XW4; g += NTHR) {
            int r = g / XW4, j = g - r * XW4;
            int gy = y0 + r - 3;
            int gx = x0 + 4 * j - 4;
            float4 v = make_float4(0.f, 0.f, 0.f, 0.f);
            if ((unsigned)gy < (unsigned)H) {
                const float* row = img + (size_t)gy * W;
                if (gx >= 0 && gx + 3 < W) {
                    v = *(const float4*)(row + gx);
                } else {
                    float* vp = &v.x;
#pragma unroll
                    for (int k = 0; k < 4; k++)
                        if ((unsigned)(gx + k) < (unsigned)W) vp[k] = row[gx + k];
                }
            }
            s_x[r][j] = v;
        }
    }
    __syncthreads();

    // ---- Phase B: gaussian into s_s (4 px per iteration) ----
    for (int g = tid; g < SROWS * 33; g += NTHR) {
        int r = g / 33, gc = g - r * 33;
        const float G[25] = {
            2.0f/159.0f, 4.0f/159.0f,  5.0f/159.0f, 4.0f/159.0f, 2.0f/159.0f,
            4.0f/159.0f, 9.0f/159.0f, 12.0f/159.0f, 9.0f/159.0f, 4.0f/159.0f,
            5.0f/159.0f,12.0f/159.0f, 15.0f/159.0f,12.0f/159.0f, 5.0f/159.0f,
            4.0f/159.0f, 9.0f/159.0f, 12.0f/159.0f, 9.0f/159.0f, 4.0f/159.0f,
            2.0f/159.0f, 4.0f/159.0f,  5.0f/159.0f, 4.0f/159.0f, 2.0f/159.0f };
        float res[4] = {0.f, 0.f, 0.f, 0.f};
#pragma unroll
        for (int dy = 0; dy < 5; dy++) {
            __align__(16) float f[12];
            *(float4*)(f + 0) = s_x[r + dy][gc];
            *(float4*)(f + 4) = s_x[r + dy][gc + 1];
            *(float4*)(f + 8) = s_x[r + dy][gc + 2];
            // x col (cs+j-2+dx) is at local idx 1+j+dx  (word base = float idx cs+1)
#pragma unroll
            for (int j = 0; j < 4; j++)
#pragma unroll
                for (int dx = 0; dx < 5; dx++)
                    res[j] = fmaf(f[1 + j + dx], G[dy * 5 + dx], res[j]);
        }
        float4 sv;
        float* sp = &sv.x;
        if (interior) {
#pragma unroll
            for (int j = 0; j < 4; j++)
                sp[j] = res[j] * (1.0f / 255.0f);
        } else {
            int cs = 4 * gc - 1;      // smoothed col group base, cs in [-1,127]
            int gy = y0 + r - 1;
#pragma unroll
            for (int j = 0; j < 4; j++) {
                int gx = x0 + cs + j;
                sp[j] = ((unsigned)gy < (unsigned)H && (unsigned)gx < (unsigned)W)
                        ? res[j] * (1.0f / 255.0f) : 0.0f;
            }
        }
        s_s[r][gc] = sv;
    }
    __syncthreads();

    // ---- Phase C: sobel + mag + angle, 4 px per iteration ----
    for (int g = tid; g < BY * 32; g += NTHR) {
        int r = g >> 5, gc = g & 31;
        int c = 4 * gc;
        __align__(16) float fm[8], f0[8], fp[8];
        *(float4*)(fm)     = s_s[r][gc];     *(float4*)(fm + 4) = s_s[r][gc + 1];
        *(float4*)(f0)     = s_s[r + 1][gc]; *(float4*)(f0 + 4) = s_s[r + 1][gc + 1];
        *(float4*)(fp)     = s_s[r + 2][gc]; *(float4*)(fp + 4) = s_s[r + 2][gc + 1];

        float4 vmag, vmag255, vang;
        unsigned int dirw = 0;
#pragma unroll
        for (int j = 0; j < 4; j++) {
            float a00 = fm[j], a01 = fm[j + 1], a02 = fm[j + 2];
            float a10 = f0[j],                  a12 = f0[j + 2];
            float a20 = fp[j], a21 = fp[j + 1], a22 = fp[j + 2];

            float gxv = 0.0f;
            gxv = fmaf(a00, -0.125f, gxv);
            gxv = fmaf(a02,  0.125f, gxv);
            gxv = fmaf(a10, -0.25f,  gxv);
            gxv = fmaf(a12,  0.25f,  gxv);
            gxv = fmaf(a20, -0.125f, gxv);
            gxv = fmaf(a22,  0.125f, gxv);

            float gyv = 0.0f;
            gyv = fmaf(a00, -0.125f, gyv);
            gyv = fmaf(a01, -0.25f,  gyv);
            gyv = fmaf(a02, -0.125f, gyv);
            gyv = fmaf(a20,  0.125f, gyv);
            gyv = fmaf(a21,  0.25f,  gyv);
            gyv = fmaf(a22,  0.125f, gyv);

            float mag = sqrtf(gxv * gxv + gyv * gyv + 1e-6f);
            float ang = fast_atan2f(gyv, gxv);

            float v = ang + CUDART_PI_F;
            const float TWOPI = 2.0f * CUDART_PI_F;
            if (v >= TWOPI) v -= TWOPI;
            float deg = v * (180.0f / CUDART_PI_F);
            int rr = (int)rintf(deg / 45.0f);
            int cls = (rr & 7) & 3;

            float adeg = deg;
            if (adeg >= 180.0f) adeg -= 180.0f;
            if (adeg >= 180.0f) adeg -= 180.0f;

            (&vmag.x)[j]    = mag;
            (&vmag255.x)[j] = mag * 255.0f;
            (&vang.x)[j]    = adeg;
            dirw |= (unsigned int)cls << (8 * j);
        }
        size_t base = (size_t)b * NPIX + (size_t)(y0 + r) * W + (x0 + c);
        *(float4*)(g_mag + base)        = vmag;
        *(float4*)(out_mag + base)      = vmag255;
        *(float4*)(out_ang + base)      = vang;
        *(unsigned int*)(g_dir + base)  = dirw;
    }
}

// ---------------------------------------------------------------------------
// K2: NMS (wrap neighbors, incl. ref's class-1 n_up bug) + 2 hysteresis
//     iterations, SIMD-in-word byte states, with data-dependent early-outs.
//     (identical to the round-12 passing kernel)
// ---------------------------------------------------------------------------
__global__ __launch_bounds__(NTHR) void k2(float* __restrict__ out_edges) {
    __shared__ float4       s_m[MROWS][MW4];
    __shared__ unsigned int s_d[DROWS][BW4];
    __shared__ unsigned int s_0[DROWS][BW4];
    __shared__ unsigned int s_1[S1ROWS][BW4];

    const int x0 = blockIdx.x * BX, y0 = blockIdx.y * BY, b = blockIdx.z;
    const int tid = threadIdx.x;
    const float* m = g_mag + (size_t)b * NPIX;
    const unsigned char* dd = g_dir + (size_t)b * NPIX;

    // ---- A1: mag tile with wrap (jnp.roll semantics) ----
    for (int g = tid; g < MROWS * MW4; g += NTHR) {
        int r = g / MW4, j = g - r * MW4;
        int gy = y0 + r - 3;
        if (gy < 0) gy += H; else if (gy >= H) gy -= H;
        int gx = x0 + 4 * j - 8;
        const float* row = m + (size_t)gy * W;
        float4 v;
        if (gx >= 0 && gx + 3 < W) {
            v = *(const float4*)(row + gx);
        } else {
            float* vp = &v.x;
#pragma unroll
            for (int k = 0; k < 4; k++) {
                int t = gx + k;
                if (t < 0) t += W; else if (t >= W) t -= W;
                vp[k] = row[t];
            }
        }
        s_m[r][j] = v;
    }
    // ---- A2: dir tile (zero outside image) ----
    for (int g = tid; g < DROWS * BW4; g += NTHR) {
        int r = g / BW4, j = g - r * BW4;
        int gy = y0 + r - 2;
        int gx = x0 + 4 * j - 8;
        unsigned int v = 0;
        if ((unsigned)gy < (unsigned)H) {
            const unsigned char* row = dd + (size_t)gy * W;
            if (gx >= 0 && gx + 3 < W) {
                v = *(const unsigned int*)(row + gx);
            } else {
#pragma unroll
                for (int k = 0; k < 4; k++)
                    if ((unsigned)(gx + k) < (unsigned)W)
                        v |= (unsigned int)row[gx + k] << (8 * k);
            }
        }
        s_d[r][j] = v;
    }
    // ---- A3: zero the unwritten edge words of s_0 ----
    for (int g = tid; g < DROWS * 2; g += NTHR)
        s_0[g >> 1][(g & 1) ? 35 : 0] = 0u;
    __syncthreads();

    // ---- B: NMS + double threshold -> packed states (2=edge,1=low,0=none) --
    const float HIGHT = 150.0f / 255.0f;
    const float LOWT  = 50.0f  / 255.0f;
    for (int g = tid; g < DROWS * 34; g += NTHR) {
        int r = g / 34, gi = g - r * 34;

        float4 cv = s_m[r + 1][gi + 1];     // the 4 center mags (cm[4..7])
        float cmax = fmaxf(fmaxf(cv.x, cv.y), fmaxf(cv.z, cv.w));
        if (cmax < LOWT) {                   // whole group suppressed
            s_0[r][gi + 1] = 0u;
            continue;
        }

        int cc = 4 * gi - 4;                 // state col group base in [-4,128]
        int gy = y0 + (r - 2);
        __align__(16) float um[12], cm[12], dm[12];
        *(float4*)(um) = s_m[r][gi];     *(float4*)(um+4) = s_m[r][gi+1];     *(float4*)(um+8) = s_m[r][gi+2];
        *(float4*)(cm) = s_m[r+1][gi];                                        *(float4*)(cm+8) = s_m[r+1][gi+2];
        *(float4*)(cm+4) = cv;
        *(float4*)(dm) = s_m[r+2][gi];   *(float4*)(dm+4) = s_m[r+2][gi+1];   *(float4*)(dm+8) = s_m[r+2][gi+2];
        unsigned int dw = s_d[r][gi + 1];
        bool rowok = (unsigned)gy < (unsigned)H;
        unsigned int word = 0;
#pragma unroll
        for (int j = 0; j < 4; j++) {
            // mag col (cc+j+d) at local idx j+4+d
            float c0 = cm[j + 4];
            int cls = (int)((dw >> (8 * j)) & 0xFF);
            float n1 = (cls == 0) ? cm[j + 5]             // R
                     : (cls == 1) ? dm[j + 5]             // DR (n_d1)
                     : (cls == 2) ? dm[j + 4]             // D
                                  : dm[j + 3];            // DL (n_d3)
            float n2 = (cls == 0) ? cm[j + 3]             // L
                     : (cls == 3) ? um[j + 5]             // UR (n_d4)
                                  : um[j + 4];            // U (cls 1 ref-bug & 2)
            int st = 0;
            if ((c0 > n1) && (c0 > n2))
                st = (c0 > HIGHT) ? 2 : ((c0 >= LOWT) ? 1 : 0);
            int gx = x0 + cc + j;
            if (!(rowok && (unsigned)gx < (unsigned)W)) st = 0;
            word |= (unsigned int)st << (8 * j);
        }
        s_0[r][gi + 1] = word;
    }
    __syncthreads();

    // ---- C: hysteresis iter 1 (snapshot, zero pad), SIMD bytes ----
    for (int g = tid; g < S1ROWS * 34; g += NTHR) {
        int r = g / 34, gi = g - r * 34;
        unsigned int ctr = s_0[r + 1][gi + 1];
        unsigned int is1 = __vcmpeq4(ctr, 0x01010101u);
        if (is1 == 0u) { s_1[r][gi + 1] = ctr; continue; }
        unsigned int mx = 0;
#pragma unroll
        for (int q = 0; q < 3; q++) {
            unsigned int p = s_0[r + q][gi], c = s_0[r + q][gi + 1], n = s_0[r + q][gi + 2];
            unsigned int lft = __byte_perm(p, c, 0x6543);
            unsigned int rgt = __byte_perm(c, n, 0x4321);
            mx = __vmaxu4(mx, __vmaxu4(lft, __vmaxu4(c, rgt)));
        }
        unsigned int nb2 = __vcmpeq4(mx, 0x02020202u);
        s_1[r][gi + 1] = ctr + (is1 & nb2 & 0x01010101u);
    }
    __syncthreads();

    // ---- D: hysteresis iter 2 + edges output (float4 stores) ----
    for (int g = tid; g < BY * 32; g += NTHR) {
        int r = g >> 5, gi = g & 31;
        int cc = 4 * gi;
        unsigned int ctr = s_1[r + 1][gi + 2];
        unsigned int is1 = __vcmpeq4(ctr, 0x01010101u);
        unsigned int res = ctr;
        if (is1 != 0u) {
            unsigned int mx = 0;
#pragma unroll
            for (int q = 0; q < 3; q++) {
                unsigned int p = s_1[r + q][gi + 1], c = s_1[r + q][gi + 2], n = s_1[r + q][gi + 3];
                unsigned int lft = __byte_perm(p, c, 0x6543);
                unsigned int rgt = __byte_perm(c, n, 0x4321);
                mx = __vmaxu4(mx, __vmaxu4(lft, __vmaxu4(c, rgt)));
            }
            unsigned int nb2 = __vcmpeq4(mx, 0x02020202u);
            res = ctr + (is1 & nb2 & 0x01010101u);
        }

        float4 o;
        float* op = &o.x;
#pragma unroll
        for (int j = 0; j < 4; j++)
            op[j] = (((res >> (8 * j)) & 0xFF) == 2u) ? 255.0f : 0.0f;
        size_t base = (size_t)b * NPIX + (size_t)(y0 + r) * W + (x0 + cc);
        *(float4*)(out_edges + base) = o;
    }
}

// ---------------------------------------------------------------------------
// Launch
// ---------------------------------------------------------------------------
extern "C" void kernel_launch(void* const* d_in, const int* in_sizes, int n_in,
                              void* d_out, int out_size) {
    const float* x = (const float*)d_in[0];
    float* out = (float*)d_out;
    float* out_edges = out;
    float* out_mag   = out + (size_t)NTOT;
    float* out_ang   = out + (size_t)2 * NTOT;

    dim3 blk(NTHR, 1, 1);
    dim3 grd(W / BX, H / BY, BATCH);   // 15 x 45 x 8

    k1<<<grd, blk>>>(x, out_mag, out_ang);
    k2<<<grd, blk>>>(out_edges);
}

// round 16
// speedup vs baseline: 1.9015x; 1.0261x over previous
#include <cuda_runtime.h>
#include <math_constants.h>

#define BATCH 8
#define H 1080
#define W 1920
#define NPIX (H * W)
#define NTOT (BATCH * NPIX)

#define BX 128
#define BY 24
#define NTHR 256

// ---- K1 tiles (float4 words) ----
#define XROWS (BY + 6)   // 30 ; x col c stored at float idx c+4, c in [-4,139]
#define XW4   36         // 144 floats
#define SROWS (BY + 2)   // 26 ; smoothed col cs at float idx cs+1
#define SW4   34         // 136 floats

// ---- K2 tiles ----
#define MROWS (BY + 6)   // 30 ; mag col c at float idx c+8, c in [-8,135]
#define MW4   36         // 144 floats
#define DROWS (BY + 4)   // 28 ; byte tiles: col c at byte idx c+8
#define BW4   36         // 144 bytes = 36 words
#define S1ROWS (BY + 2)  // 26

// Scratch (device globals — no allocations allowed)
__device__ unsigned char g_dir[NTOT];

// ---------------------------------------------------------------------------
// Fast atan2 (Cephes-style): ~2e-7 rad accuracy.
// ---------------------------------------------------------------------------
__device__ __forceinline__ float fast_atan2f(float gy, float gx) {
    float ax = fabsf(gx), ay = fabsf(gy);
    float mx = fmaxf(ax, ay), mn = fminf(ax, ay);
    float t = (mx == 0.0f) ? 0.0f : __fdividef(mn, mx);   // [0,1]
    bool red = t > 0.41421356f;                            // tan(pi/8)
    float tr = __fdividef(t - 1.0f, t + 1.0f);             // (-0.2929, 0]
    float z = red ? tr : t;
    float s = z * z;
    float p = fmaf(s, fmaf(s, fmaf(s, 8.05374449538e-2f,
                                     -1.38776856032e-1f),
                               1.99777106479e-1f),
                     -3.33329491539e-1f);
    float a = fmaf(z * s, p, z);                           // atan(z)
    if (red) a += 0.78539816339744831f;                    // + pi/4
    if (ay > ax) a = 1.57079632679489662f - a;             // pi/2 - a
    if (gx < 0.0f) a = CUDART_PI_F - a;                    // pi - a
    return copysignf(a, gy);
}

// ---------------------------------------------------------------------------
// K1: fused x/255 -> gaussian 5x5 (zero pad) -> sobel (zero pad) -> mag/ang/cls
// Writes ONLY out_mag (mag*255), out_ang, g_dir. (g_mag stream eliminated.)
// ---------------------------------------------------------------------------
__global__ __launch_bounds__(NTHR) void k1(const float* __restrict__ x,
                                           float* __restrict__ out_mag,
                                           float* __restrict__ out_ang) {
    __shared__ float4 s_x[XROWS][XW4];
    __shared__ float4 s_s[SROWS][SW4];

    const int x0 = blockIdx.x * BX, y0 = blockIdx.y * BY, b = blockIdx.z;
    const int tid = threadIdx.x;
    const float* img = x + (size_t)b * NPIX;

    const bool interior = (x0 >= 4) && (x0 + 140 <= W) &&
                          (y0 >= 3) && (y0 + 27 <= H);

    // ---- Phase A: load x tile (halo), vectorized ----
    if (interior) {
        for (int g = tid; g < XROWS * XW4; g += NTHR) {
            int r = g / XW4, j = g - r * XW4;
            const float* row = img + (size_t)(y0 + r - 3) * W + (x0 - 4);
            s_x[r][j] = *(const float4*)(row + 4 * j);
        }
    } else {
        for (int g = tid; g < XROWS * XW4; g += NTHR) {
            int r = g / XW4, j = g - r * XW4;
            int gy = y0 + r - 3;
            int gx = x0 + 4 * j - 4;
            float4 v = make_float4(0.f, 0.f, 0.f, 0.f);
            if ((unsigned)gy < (unsigned)H) {
                const float* row = img + (size_t)gy * W;
                if (gx >= 0 && gx + 3 < W) {
                    v = *(const float4*)(row + gx);
                } else {
                    float* vp = &v.x;
#pragma unroll
                    for (int k = 0; k < 4; k++)
                        if ((unsigned)(gx + k) < (unsigned)W) vp[k] = row[gx + k];
                }
            }
            s_x[r][j] = v;
        }
    }
    __syncthreads();

    // ---- Phase B: gaussian into s_s (4 px per iteration) ----
    for (int g = tid; g < SROWS * 33; g += NTHR) {
        int r = g / 33, gc = g - r * 33;
        const float G[25] = {
            2.0f/159.0f, 4.0f/159.0f,  5.0f/159.0f, 4.0f/159.0f, 2.0f/159.0f,
            4.0f/159.0f, 9.0f/159.0f, 12.0f/159.0f, 9.0f/159.0f, 4.0f/159.0f,
            5.0f/159.0f,12.0f/159.0f, 15.0f/159.0f,12.0f/159.0f, 5.0f/159.0f,
            4.0f/159.0f, 9.0f/159.0f, 12.0f/159.0f, 9.0f/159.0f, 4.0f/159.0f,
            2.0f/159.0f, 4.0f/159.0f,  5.0f/159.0f, 4.0f/159.0f, 2.0f/159.0f };
        float res[4] = {0.f, 0.f, 0.f, 0.f};
#pragma unroll
        for (int dy = 0; dy < 5; dy++) {
            __align__(16) float f[12];
            *(float4*)(f + 0) = s_x[r + dy][gc];
            *(float4*)(f + 4) = s_x[r + dy][gc + 1];
            *(float4*)(f + 8) = s_x[r + dy][gc + 2];
#pragma unroll
            for (int j = 0; j < 4; j++)
#pragma unroll
                for (int dx = 0; dx < 5; dx++)
                    res[j] = fmaf(f[1 + j + dx], G[dy * 5 + dx], res[j]);
        }
        float4 sv;
        float* sp = &sv.x;
        if (interior) {
#pragma unroll
            for (int j = 0; j < 4; j++)
                sp[j] = res[j] * (1.0f / 255.0f);
        } else {
            int cs = 4 * gc - 1;
            int gy = y0 + r - 1;
#pragma unroll
            for (int j = 0; j < 4; j++) {
                int gx = x0 + cs + j;
                sp[j] = ((unsigned)gy < (unsigned)H && (unsigned)gx < (unsigned)W)
                        ? res[j] * (1.0f / 255.0f) : 0.0f;
            }
        }
        s_s[r][gc] = sv;
    }
    __syncthreads();

    // ---- Phase C: sobel + mag + angle, 4 px per iteration ----
    for (int g = tid; g < BY * 32; g += NTHR) {
        int r = g >> 5, gc = g & 31;
        int c = 4 * gc;
        __align__(16) float fm[8], f0[8], fp[8];
        *(float4*)(fm)     = s_s[r][gc];     *(float4*)(fm + 4) = s_s[r][gc + 1];
        *(float4*)(f0)     = s_s[r + 1][gc]; *(float4*)(f0 + 4) = s_s[r + 1][gc + 1];
        *(float4*)(fp)     = s_s[r + 2][gc]; *(float4*)(fp + 4) = s_s[r + 2][gc + 1];

        float4 vmag255, vang;
        unsigned int dirw = 0;
#pragma unroll
        for (int j = 0; j < 4; j++) {
            float a00 = fm[j], a01 = fm[j + 1], a02 = fm[j + 2];
            float a10 = f0[j],                  a12 = f0[j + 2];
            float a20 = fp[j], a21 = fp[j + 1], a22 = fp[j + 2];

            float gxv = 0.0f;
            gxv = fmaf(a00, -0.125f, gxv);
            gxv = fmaf(a02,  0.125f, gxv);
            gxv = fmaf(a10, -0.25f,  gxv);
            gxv = fmaf(a12,  0.25f,  gxv);
            gxv = fmaf(a20, -0.125f, gxv);
            gxv = fmaf(a22,  0.125f, gxv);

            float gyv = 0.0f;
            gyv = fmaf(a00, -0.125f, gyv);
            gyv = fmaf(a01, -0.25f,  gyv);
            gyv = fmaf(a02, -0.125f, gyv);
            gyv = fmaf(a20,  0.125f, gyv);
            gyv = fmaf(a21,  0.25f,  gyv);
            gyv = fmaf(a22,  0.125f, gyv);

            float mag = sqrtf(gxv * gxv + gyv * gyv + 1e-6f);
            float ang = fast_atan2f(gyv, gxv);

            float v = ang + CUDART_PI_F;
            const float TWOPI = 2.0f * CUDART_PI_F;
            if (v >= TWOPI) v -= TWOPI;
            float deg = v * (180.0f / CUDART_PI_F);
            int rr = (int)rintf(deg / 45.0f);
            int cls = (rr & 7) & 3;

            float adeg = deg;
            if (adeg >= 180.0f) adeg -= 180.0f;
            if (adeg >= 180.0f) adeg -= 180.0f;

            (&vmag255.x)[j] = mag * 255.0f;
            (&vang.x)[j]    = adeg;
            dirw |= (unsigned int)cls << (8 * j);
        }
        size_t base = (size_t)b * NPIX + (size_t)(y0 + r) * W + (x0 + c);
        *(float4*)(out_mag + base)      = vmag255;
        *(float4*)(out_ang + base)      = vang;
        *(unsigned int*)(g_dir + base)  = dirw;
    }
}

// ---------------------------------------------------------------------------
// K2: NMS (wrap neighbors, incl. ref's class-1 n_up bug) + 2 hysteresis
//     iterations. Reads out_mag (mag*255) — thresholds at the x255 scale.
// ---------------------------------------------------------------------------
__global__ __launch_bounds__(NTHR) void k2(const float* __restrict__ mag255,
                                           float* __restrict__ out_edges) {
    __shared__ float4       s_m[MROWS][MW4];
    __shared__ unsigned int s_d[DROWS][BW4];
    __shared__ unsigned int s_0[DROWS][BW4];
    __shared__ unsigned int s_1[S1ROWS][BW4];

    const int x0 = blockIdx.x * BX, y0 = blockIdx.y * BY, b = blockIdx.z;
    const int tid = threadIdx.x;
    const float* m = mag255 + (size_t)b * NPIX;
    const unsigned char* dd = g_dir + (size_t)b * NPIX;

    // ---- A1: mag tile with wrap (jnp.roll semantics) ----
    for (int g = tid; g < MROWS * MW4; g += NTHR) {
        int r = g / MW4, j = g - r * MW4;
        int gy = y0 + r - 3;
        if (gy < 0) gy += H; else if (gy >= H) gy -= H;
        int gx = x0 + 4 * j - 8;
        const float* row = m + (size_t)gy * W;
        float4 v;
        if (gx >= 0 && gx + 3 < W) {
            v = *(const float4*)(row + gx);
        } else {
            float* vp = &v.x;
#pragma unroll
            for (int k = 0; k < 4; k++) {
                int t = gx + k;
                if (t < 0) t += W; else if (t >= W) t -= W;
                vp[k] = row[t];
            }
        }
        s_m[r][j] = v;
    }
    // ---- A2: dir tile (zero outside image) ----
    for (int g = tid; g < DROWS * BW4; g += NTHR) {
        int r = g / BW4, j = g - r * BW4;
        int gy = y0 + r - 2;
        int gx = x0 + 4 * j - 8;
        unsigned int v = 0;
        if ((unsigned)gy < (unsigned)H) {
            const unsigned char* row = dd + (size_t)gy * W;
            if (gx >= 0 && gx + 3 < W) {
                v = *(const unsigned int*)(row + gx);
            } else {
#pragma unroll
                for (int k = 0; k < 4; k++)
                    if ((unsigned)(gx + k) < (unsigned)W)
                        v |= (unsigned int)row[gx + k] << (8 * k);
            }
        }
        s_d[r][j] = v;
    }
    // ---- A3: zero the unwritten edge words of s_0 ----
    for (int g = tid; g < DROWS * 2; g += NTHR)
        s_0[g >> 1][(g & 1) ? 35 : 0] = 0u;
    __syncthreads();

    // ---- B: NMS + double threshold -> packed states (2=edge,1=low,0=none) --
    // Thresholds at x255 scale (mag values here are mag*255).
    const float HIGHT = 150.0f;
    const float LOWT  = 50.0f;
    for (int g = tid; g < DROWS * 34; g += NTHR) {
        int r = g / 34, gi = g - r * 34;

        float4 cv = s_m[r + 1][gi + 1];     // the 4 center mags (cm[4..7])
        float cmax = fmaxf(fmaxf(cv.x, cv.y), fmaxf(cv.z, cv.w));
        if (cmax < LOWT) {                   // whole group suppressed
            s_0[r][gi + 1] = 0u;
            continue;
        }

        int cc = 4 * gi - 4;                 // state col group base in [-4,128]
        int gy = y0 + (r - 2);
        __align__(16) float um[12], cm[12], dm[12];
        *(float4*)(um) = s_m[r][gi];     *(float4*)(um+4) = s_m[r][gi+1];     *(float4*)(um+8) = s_m[r][gi+2];
        *(float4*)(cm) = s_m[r+1][gi];                                        *(float4*)(cm+8) = s_m[r+1][gi+2];
        *(float4*)(cm+4) = cv;
        *(float4*)(dm) = s_m[r+2][gi];   *(float4*)(dm+4) = s_m[r+2][gi+1];   *(float4*)(dm+8) = s_m[r+2][gi+2];
        unsigned int dw = s_d[r][gi + 1];
        bool rowok = (unsigned)gy < (unsigned)H;
        unsigned int word = 0;
#pragma unroll
        for (int j = 0; j < 4; j++) {
            // mag col (cc+j+d) at local idx j+4+d
            float c0 = cm[j + 4];
            int cls = (int)((dw >> (8 * j)) & 0xFF);
            float n1 = (cls == 0) ? cm[j + 5]             // R
                     : (cls == 1) ? dm[j + 5]             // DR (n_d1)
                     : (cls == 2) ? dm[j + 4]             // D
                                  : dm[j + 3];            // DL (n_d3)
            float n2 = (cls == 0) ? cm[j + 3]             // L
                     : (cls == 3) ? um[j + 5]             // UR (n_d4)
                                  : um[j + 4];            // U (cls 1 ref-bug & 2)
            int st = 0;
            if ((c0 > n1) && (c0 > n2))
                st = (c0 > HIGHT) ? 2 : ((c0 >= LOWT) ? 1 : 0);
            int gx = x0 + cc + j;
            if (!(rowok && (unsigned)gx < (unsigned)W)) st = 0;
            word |= (unsigned int)st << (8 * j);
        }
        s_0[r][gi + 1] = word;
    }
    __syncthreads();

    // ---- C: hysteresis iter 1 (snapshot, zero pad), SIMD bytes ----
    for (int g = tid; g < S1ROWS * 34; g += NTHR) {
        int r = g / 34, gi = g - r * 34;
        unsigned int ctr = s_0[r + 1][gi + 1];
        unsigned int is1 = __vcmpeq4(ctr, 0x01010101u);
        if (is1 == 0u) { s_1[r][gi + 1] = ctr; continue; }
        unsigned int mx = 0;
#pragma unroll
        for (int q = 0; q < 3; q++) {
            unsigned int p = s_0[r + q][gi], c = s_0[r + q][gi + 1], n = s_0[r + q][gi + 2];
            unsigned int lft = __byte_perm(p, c, 0x6543);
            unsigned int rgt = __byte_perm(c, n, 0x4321);
            mx = __vmaxu4(mx, __vmaxu4(lft, __vmaxu4(c, rgt)));
        }
        unsigned int nb2 = __vcmpeq4(mx, 0x02020202u);
        s_1[r][gi + 1] = ctr + (is1 & nb2 & 0x01010101u);
    }
    __syncthreads();

    // ---- D: hysteresis iter 2 + edges output (float4 stores) ----
    for (int g = tid; g < BY * 32; g += NTHR) {
        int r = g >> 5, gi = g & 31;
        int cc = 4 * gi;
        unsigned int ctr = s_1[r + 1][gi + 2];
        unsigned int is1 = __vcmpeq4(ctr, 0x01010101u);
        unsigned int res = ctr;
        if (is1 != 0u) {
            unsigned int mx = 0;
#pragma unroll
            for (int q = 0; q < 3; q++) {
                unsigned int p = s_1[r + q][gi + 1], c = s_1[r + q][gi + 2], n = s_1[r + q][gi + 3];
                unsigned int lft = __byte_perm(p, c, 0x6543);
                unsigned int rgt = __byte_perm(c, n, 0x4321);
                mx = __vmaxu4(mx, __vmaxu4(lft, __vmaxu4(c, rgt)));
            }
            unsigned int nb2 = __vcmpeq4(mx, 0x02020202u);
            res = ctr + (is1 & nb2 & 0x01010101u);
        }

        float4 o;
        float* op = &o.x;
#pragma unroll
        for (int j = 0; j < 4; j++)
            op[j] = (((res >> (8 * j)) & 0xFF) == 2u) ? 255.0f : 0.0f;
        size_t base = (size_t)b * NPIX + (size_t)(y0 + r) * W + (x0 + cc);
        *(float4*)(out_edges + base) = o;
    }
}

// ---------------------------------------------------------------------------
// Launch
// ---------------------------------------------------------------------------
extern "C" void kernel_launch(void* const* d_in, const int* in_sizes, int n_in,
                              void* d_out, int out_size) {
    const float* x = (const float*)d_in[0];
    float* out = (float*)d_out;
    float* out_edges = out;
    float* out_mag   = out + (size_t)NTOT;
    float* out_ang   = out + (size_t)2 * NTOT;

    dim3 blk(NTHR, 1, 1);
    dim3 grd(W / BX, H / BY, BATCH);   // 15 x 45 x 8

    k1<<<grd, blk>>>(x, out_mag, out_ang);
    k2<<<grd, blk>>>(out_mag, out_edges);
}